// round 8
// baseline (speedup 1.0000x reference)
#include <cuda_runtime.h>
#include <cuda_fp16.h>
#include <cstdint>

#define B_ROWS 16384
#define C_DIM  1024
#define N_ITERS 16

// ---- GEMM config: 256x128 tile, BK=64 halves, 3-stage cp.async, 512 threads ----
#define TILE_M 256
#define TILE_N 128
#define BKC    64
#define NSTAGE 3
#define A_STAGE_BYTES (TILE_M * 128)    // 32KB
#define B_STAGE_BYTES (TILE_N * 128)    // 16KB
#define STAGE_BYTES   (A_STAGE_BYTES + B_STAGE_BYTES)
#define SMEM_TOTAL    (NSTAGE * STAGE_BYTES + 1024)
#define KCHUNKS       (C_DIM / BKC)
#define GEMM_THREADS  512

// ---------------- static scratch ----------------
__device__ __half g_h1[(size_t)B_ROWS * C_DIM];
__device__ __half g_h2[(size_t)B_ROWS * C_DIM];
__device__ __half g_t1[(size_t)B_ROWS * C_DIM];
__device__ __half g_t2[(size_t)B_ROWS * C_DIM];
__device__ __half g_yh[(size_t)B_ROWS * C_DIM];
__device__ __half g_vh[(size_t)B_ROWS * C_DIM];
__device__ __half g_d1[(size_t)B_ROWS * C_DIM];
__device__ __half g_d2[(size_t)B_ROWS * C_DIM];
__device__ __half g_u [(size_t)B_ROWS * C_DIM];          // u = v @ W1^T (fp16)
__device__ __half g_w1h [(size_t)C_DIM * C_DIM];
__device__ __half g_w2h [(size_t)C_DIM * C_DIM];
__device__ __half g_w3h [(size_t)C_DIM * C_DIM];
__device__ __half g_w2th[(size_t)C_DIM * C_DIM];
__device__ __half g_w3th[(size_t)C_DIM * C_DIM];
__device__ __half g_m13 [(size_t)C_DIM * C_DIM];         // M[n,c] = (W1·W3)[c,n]

// ---------------- helpers ----------------
__device__ __forceinline__ uint32_t smem_u32(const void* p) {
    uint32_t a;
    asm("{ .reg .u64 t; cvta.to.shared.u64 t, %1; cvt.u32.u64 %0, t; }" : "=r"(a) : "l"(p));
    return a;
}

#define LDSM4(R0, R1, R2, R3, addr)                                                 \
    asm volatile("ldmatrix.sync.aligned.m8n8.x4.shared.b16 {%0,%1,%2,%3}, [%4];"    \
                 : "=r"(R0), "=r"(R1), "=r"(R2), "=r"(R3) : "r"(addr))

#define MMA_F16(C0, C1, C2, C3, A0, A1, A2, A3, Bb0, Bb1)                           \
    asm volatile(                                                                   \
        "mma.sync.aligned.m16n8k16.row.col.f32.f16.f16.f32 "                        \
        "{%0,%1,%2,%3}, {%4,%5,%6,%7}, {%8,%9}, {%0,%1,%2,%3};"                     \
        : "+f"(C0), "+f"(C1), "+f"(C2), "+f"(C3)                                    \
        : "r"(A0), "r"(A1), "r"(A2), "r"(A3), "r"(Bb0), "r"(Bb1))

constexpr int EPI_ELU      = 0;  // out0(h) = elu(c+bias), out1(h) = elu'
constexpr int EPI_ADDY     = 1;  // out0(f) = aux(f) + c + bias
constexpr int EPI_MULD     = 2;  // out0(h) = c * aux(h)
constexpr int EPI_MULD_DOT = 3;  // val = c*aux(h); out0(h)=val; acc += alpha*sum(val*aux2(h))
constexpr int EPI_STOREH   = 4;  // out0(h) = c

// NT GEMM: out[m,n] = sum_k A[m,k] * Bm[n,k]
template <int EPI>
__global__ void __launch_bounds__(GEMM_THREADS, 1)
gemm_nt(const __half* __restrict__ A, const __half* __restrict__ Bm,
        const float* __restrict__ bias,
        void* __restrict__ out0, void* __restrict__ out1,
        const void* __restrict__ aux, const __half* __restrict__ aux2,
        float alpha, float* __restrict__ acc)
{
    extern __shared__ __align__(16) char dsm[];
    const uint32_t sbase = (smem_u32(dsm) + 1023u) & ~1023u;

    const int tid  = threadIdx.x;
    const int lane = tid & 31;
    const int warp = tid >> 5;
    const int wm   = warp & 7;   // 8 warps along M (32 rows each)
    const int wn   = warp >> 3;  // 2 warps along N (64 cols each)
    const int g    = lane >> 2;
    const int t    = lane & 3;

    const int Lrow  = (lane & 7) | (((lane >> 3) & 1) << 3);
    const int khalf = lane >> 4;
    const int r7    = Lrow & 7;

    const int brow = blockIdx.y * TILE_M;
    const int bcol = blockIdx.x * TILE_N;
    const __half* Abase = A  + (size_t)brow * C_DIM;
    const __half* Bbase = Bm + (size_t)bcol * C_DIM;

    float c[2][8][4];
#pragma unroll
    for (int i = 0; i < 2; ++i)
#pragma unroll
        for (int j = 0; j < 8; ++j)
#pragma unroll
            for (int r = 0; r < 4; ++r) c[i][j][r] = 0.f;

// stage fill: A 256 rows x 128B (4 iters), B 128 rows x 128B (2 iters); 16B per thread-iter
#define LOADCH(ch, st)                                                            \
    do {                                                                          \
        const uint32_t sa_ = sbase + (st) * STAGE_BYTES;                          \
        const uint32_t sb_ = sa_ + A_STAGE_BYTES;                                 \
        const __half* ag_ = Abase + (ch) * BKC;                                   \
        const __half* bg_ = Bbase + (ch) * BKC;                                   \
        _Pragma("unroll")                                                         \
        for (int i_ = 0; i_ < 4; ++i_) {                                          \
            int l_ = i_ * GEMM_THREADS + tid; int r_ = l_ >> 3; int q_ = l_ & 7;  \
            uint32_t d_ = sa_ + (uint32_t)(r_ * 128) + (uint32_t)((q_ ^ (r_ & 7)) << 4); \
            const __half* s_ = ag_ + (size_t)r_ * C_DIM + q_ * 8;                 \
            asm volatile("cp.async.cg.shared.global [%0], [%1], 16;"              \
                         :: "r"(d_), "l"(s_) : "memory");                         \
        }                                                                         \
        _Pragma("unroll")                                                         \
        for (int i_ = 0; i_ < 2; ++i_) {                                          \
            int l_ = i_ * GEMM_THREADS + tid; int r_ = l_ >> 3; int q_ = l_ & 7;  \
            uint32_t d_ = sb_ + (uint32_t)(r_ * 128) + (uint32_t)((q_ ^ (r_ & 7)) << 4); \
            const __half* s_ = bg_ + (size_t)r_ * C_DIM + q_ * 8;                 \
            asm volatile("cp.async.cg.shared.global [%0], [%1], 16;"              \
                         :: "r"(d_), "l"(s_) : "memory");                         \
        }                                                                         \
        asm volatile("cp.async.commit_group;" ::: "memory");                      \
    } while (0)

    LOADCH(0, 0);
    LOADCH(1, 1);

#pragma unroll 1
    for (int ch = 0; ch < KCHUNKS; ++ch) {
        const int s = ch % NSTAGE;
        asm volatile("cp.async.wait_group 1;" ::: "memory");
        __syncthreads();

        if (ch + 2 < KCHUNKS) {
            const int s2 = (ch + 2) % NSTAGE;
            LOADCH(ch + 2, s2);
        } else {
            asm volatile("cp.async.commit_group;" ::: "memory");
        }

        const uint32_t sa = sbase + s * STAGE_BYTES;
        const uint32_t sb = sa + A_STAGE_BYTES;

        uint32_t arow[2], brow4[4];
#pragma unroll
        for (int mt = 0; mt < 2; ++mt)
            arow[mt] = sa + (uint32_t)((wm * 32 + mt * 16 + Lrow) * 128);
#pragma unroll
        for (int n2 = 0; n2 < 4; ++n2)
            brow4[n2] = sb + (uint32_t)((wn * 64 + n2 * 16 + Lrow) * 128);

#pragma unroll
        for (int ks = 0; ks < 4; ++ks) {
            const uint32_t xoff = (uint32_t)(((2 * ks + khalf) ^ r7) << 4);

            unsigned af[2][4];
#pragma unroll
            for (int mt = 0; mt < 2; ++mt)
                LDSM4(af[mt][0], af[mt][1], af[mt][2], af[mt][3], arow[mt] + xoff);

            unsigned bf[8][2];
#pragma unroll
            for (int n2 = 0; n2 < 4; ++n2)
                LDSM4(bf[2 * n2][0], bf[2 * n2 + 1][0],
                      bf[2 * n2][1], bf[2 * n2 + 1][1], brow4[n2] + xoff);

#pragma unroll
            for (int mt = 0; mt < 2; ++mt)
#pragma unroll
                for (int nt = 0; nt < 8; ++nt)
                    MMA_F16(c[mt][nt][0], c[mt][nt][1], c[mt][nt][2], c[mt][nt][3],
                            af[mt][0], af[mt][1], af[mt][2], af[mt][3],
                            bf[nt][0], bf[nt][1]);
        }
    }
#undef LOADCH

    // ---------------- epilogue ----------------
    float rs[2][2];
    rs[0][0] = rs[0][1] = rs[1][0] = rs[1][1] = 0.f;

#pragma unroll
    for (int mt = 0; mt < 2; ++mt) {
        const int row0 = brow + wm * 32 + mt * 16 + g;
#pragma unroll
        for (int nt = 0; nt < 8; ++nt) {
            const int col = bcol + wn * 64 + nt * 8 + 2 * t;
#pragma unroll
            for (int h = 0; h < 2; ++h) {
                const int row = row0 + h * 8;
                const size_t idx = (size_t)row * C_DIM + col;
                float v0 = c[mt][nt][h * 2 + 0];
                float v1 = c[mt][nt][h * 2 + 1];
                if (EPI == EPI_ELU) {
                    float2 bb = *(const float2*)&bias[col];
                    float a0 = v0 + bb.x, a1 = v1 + bb.y;
                    float h0 = (a0 > 0.f) ? a0 : expm1f(a0);
                    float h1 = (a1 > 0.f) ? a1 : expm1f(a1);
                    float e0 = (a0 > 0.f) ? 1.f : h0 + 1.f;
                    float e1 = (a1 > 0.f) ? 1.f : h1 + 1.f;
                    *(__half2*)((__half*)out0 + idx) = __floats2half2_rn(h0, h1);
                    *(__half2*)((__half*)out1 + idx) = __floats2half2_rn(e0, e1);
                } else if (EPI == EPI_ADDY) {
                    float2 bb = *(const float2*)&bias[col];
                    float2 yv = *(const float2*)((const float*)aux + idx);
                    *(float2*)((float*)out0 + idx) =
                        make_float2(v0 + bb.x + yv.x, v1 + bb.y + yv.y);
                } else if (EPI == EPI_MULD) {
                    float2 dv = __half22float2(*(const __half2*)((const __half*)aux + idx));
                    *(__half2*)((__half*)out0 + idx) = __floats2half2_rn(v0 * dv.x, v1 * dv.y);
                } else if (EPI == EPI_MULD_DOT) {
                    float2 dv = __half22float2(*(const __half2*)((const __half*)aux + idx));
                    float n0 = v0 * dv.x, n1 = v1 * dv.y;
                    *(__half2*)((__half*)out0 + idx) = __floats2half2_rn(n0, n1);
                    float2 uu = __half22float2(*(const __half2*)(aux2 + idx));
                    rs[mt][h] += n0 * uu.x + n1 * uu.y;
                } else {  // EPI_STOREH
                    *(__half2*)((__half*)out0 + idx) = __floats2half2_rn(v0, v1);
                }
            }
        }
    }

    if (EPI == EPI_MULD_DOT) {
#pragma unroll
        for (int mt = 0; mt < 2; ++mt)
#pragma unroll
            for (int h = 0; h < 2; ++h) {
                float s = rs[mt][h];
                s += __shfl_xor_sync(0xffffffffu, s, 1);
                s += __shfl_xor_sync(0xffffffffu, s, 2);
                if (t == 0)
                    atomicAdd(&acc[brow + wm * 32 + mt * 16 + g + h * 8], alpha * s);
            }
    }
}

// ---------------- aux kernels ----------------
__global__ void transpose_f2h(const float* __restrict__ in, __half* __restrict__ out)
{
    __shared__ float tile[32][33];
    int x = blockIdx.x * 32 + threadIdx.x;
    int y = blockIdx.y * 32 + threadIdx.y;
#pragma unroll
    for (int i = 0; i < 32; i += 8)
        tile[threadIdx.y + i][threadIdx.x] = in[(size_t)(y + i) * C_DIM + x];
    __syncthreads();
    x = blockIdx.y * 32 + threadIdx.x;
    y = blockIdx.x * 32 + threadIdx.y;
#pragma unroll
    for (int i = 0; i < 32; i += 8)
        out[(size_t)(y + i) * C_DIM + x] = __float2half_rn(tile[threadIdx.x][threadIdx.y + i]);
}

__global__ void f2h_copy(const float* __restrict__ in, __half* __restrict__ out)
{
    int i = (blockIdx.x * 256 + threadIdx.x) * 4;
    float4 v = *(const float4*)(in + i);
    __half2 lo = __floats2half2_rn(v.x, v.y);
    __half2 hi = __floats2half2_rn(v.z, v.w);
    *(uint2*)(out + i) = make_uint2(*(unsigned*)&lo, *(unsigned*)&hi);
}

__global__ void copy_f32(const float* __restrict__ in, float* __restrict__ out, int n)
{
    int i = blockIdx.x * blockDim.x + threadIdx.x;
    if (i < n) out[i] = in[i];
}

// ---------------- launch ----------------
extern "C" void kernel_launch(void* const* d_in, const int* in_sizes, int n_in,
                              void* d_out, int out_size)
{
    (void)in_sizes; (void)n_in; (void)out_size;

    const float* y   = (const float*)d_in[0];
    const float* ldj = (const float*)d_in[1];
    const float* v   = (const float*)d_in[2];
    const float* W1  = (const float*)d_in[3];
    const float* b1  = (const float*)d_in[4];
    const float* W2  = (const float*)d_in[5];
    const float* b2  = (const float*)d_in[6];
    const float* W3  = (const float*)d_in[7];
    const float* b3  = (const float*)d_in[8];

    float* zout  = (float*)d_out;
    float* ldout = zout + (size_t)B_ROWS * C_DIM;

    __half *h1, *h2, *t1, *t2, *yh, *vh, *d1, *d2, *m13, *u;
    __half *w1h, *w2h, *w3h, *w2th, *w3th;
    cudaGetSymbolAddress((void**)&h1,   g_h1);
    cudaGetSymbolAddress((void**)&h2,   g_h2);
    cudaGetSymbolAddress((void**)&t1,   g_t1);
    cudaGetSymbolAddress((void**)&t2,   g_t2);
    cudaGetSymbolAddress((void**)&yh,   g_yh);
    cudaGetSymbolAddress((void**)&vh,   g_vh);
    cudaGetSymbolAddress((void**)&d1,   g_d1);
    cudaGetSymbolAddress((void**)&d2,   g_d2);
    cudaGetSymbolAddress((void**)&u,    g_u);
    cudaGetSymbolAddress((void**)&m13,  g_m13);
    cudaGetSymbolAddress((void**)&w1h,  g_w1h);
    cudaGetSymbolAddress((void**)&w2h,  g_w2h);
    cudaGetSymbolAddress((void**)&w3h,  g_w3h);
    cudaGetSymbolAddress((void**)&w2th, g_w2th);
    cudaGetSymbolAddress((void**)&w3th, g_w3th);

    cudaFuncSetAttribute(gemm_nt<EPI_ELU     >, cudaFuncAttributeMaxDynamicSharedMemorySize, SMEM_TOTAL);
    cudaFuncSetAttribute(gemm_nt<EPI_ADDY    >, cudaFuncAttributeMaxDynamicSharedMemorySize, SMEM_TOTAL);
    cudaFuncSetAttribute(gemm_nt<EPI_MULD    >, cudaFuncAttributeMaxDynamicSharedMemorySize, SMEM_TOTAL);
    cudaFuncSetAttribute(gemm_nt<EPI_MULD_DOT>, cudaFuncAttributeMaxDynamicSharedMemorySize, SMEM_TOTAL);
    cudaFuncSetAttribute(gemm_nt<EPI_STOREH  >, cudaFuncAttributeMaxDynamicSharedMemorySize, SMEM_TOTAL);

    dim3 tgrid(C_DIM / 32, C_DIM / 32), tblk(32, 8);
    const int wn = C_DIM * C_DIM / 1024;
    const int bn = B_ROWS * C_DIM / 1024;

    // 5 prep launches, so the 6th launch (first main GEMM) is what ncu -s 5 -c 1 profiles
    f2h_copy<<<wn, 256>>>(W1, w1h);
    f2h_copy<<<bn, 256>>>(y, yh);
    f2h_copy<<<bn, 256>>>(v, vh);
    transpose_f2h<<<tgrid, tblk>>>(W2, w2th);
    transpose_f2h<<<tgrid, tblk>>>(W3, w3th);

    dim3 ggrid(C_DIM / TILE_N, B_ROWS / TILE_M);   // (8, 64)
    dim3 sgrid(C_DIM / TILE_N, C_DIM / TILE_M);    // (8, 4)

    // launch #6 (profiled): forward layer 1
    gemm_nt<EPI_ELU ><<<ggrid, GEMM_THREADS, SMEM_TOTAL>>>(yh, w1h, b1, h1, d1, nullptr, nullptr, 0.f, nullptr);

    // remaining prep (before their consumers)
    f2h_copy<<<wn, 256>>>(W2, w2h);
    f2h_copy<<<wn, 256>>>(W3, w3h);
    copy_f32<<<B_ROWS / 256, 256>>>(ldj, ldout, B_ROWS);

    gemm_nt<EPI_ELU ><<<ggrid, GEMM_THREADS, SMEM_TOTAL>>>(h1, w2h, b2, h2, d2, nullptr, nullptr, 0.f, nullptr);
    gemm_nt<EPI_ADDY><<<ggrid, GEMM_THREADS, SMEM_TOTAL>>>(h2, w3h, b3, zout, nullptr, y, nullptr, 0.f, nullptr);

    // u = v @ W1^T (fp16)
    gemm_nt<EPI_STOREH><<<ggrid, GEMM_THREADS, SMEM_TOTAL>>>(vh, w1h, nullptr, u, nullptr, nullptr, nullptr, 0.f, nullptr);

    // M[n,c] = (W1·W3)[c,n]
    gemm_nt<EPI_STOREH><<<sgrid, GEMM_THREADS, SMEM_TOTAL>>>(w3th, w1h, nullptr, m13, nullptr, nullptr, nullptr, 0.f, nullptr);

    // power-series iterations: 2 GEMMs per k
    for (int k = 1; k <= N_ITERS; ++k) {
        if (k == 1)
            gemm_nt<EPI_MULD><<<ggrid, GEMM_THREADS, SMEM_TOTAL>>>(vh, w3th, nullptr, t1, nullptr, d2, nullptr, 0.f, nullptr);
        else
            gemm_nt<EPI_MULD><<<ggrid, GEMM_THREADS, SMEM_TOTAL>>>(t2, m13, nullptr, t1, nullptr, d2, nullptr, 0.f, nullptr);
        const float alpha = ((k & 1) ? 1.f : -1.f) / (float)k;
        gemm_nt<EPI_MULD_DOT><<<ggrid, GEMM_THREADS, SMEM_TOTAL>>>(t1, w2th, nullptr, t2, nullptr, d1, u, alpha, ldout);
    }
}

// round 9
// speedup vs baseline: 1.2849x; 1.2849x over previous
#include <cuda_runtime.h>
#include <cuda_fp16.h>
#include <cstdint>

#define B_ROWS 16384
#define C_DIM  1024
#define N_ITERS 16

// ---- GEMM config: 128x128 tile, BK=64 halves, 3-stage cp.async, 256 threads, occ 2 ----
#define TILE_M 128
#define TILE_N 128
#define BKC    64
#define NSTAGE 3
#define A_STAGE_BYTES (TILE_M * 128)
#define B_STAGE_BYTES (TILE_N * 128)
#define STAGE_BYTES   (A_STAGE_BYTES + B_STAGE_BYTES)
#define SMEM_TOTAL    (NSTAGE * STAGE_BYTES + 1024)
#define KCHUNKS       (C_DIM / BKC)
#define GEMM_THREADS  256

// ---------------- static scratch ----------------
__device__ __half g_h1[(size_t)B_ROWS * C_DIM];
__device__ __half g_h2[(size_t)B_ROWS * C_DIM];
__device__ __half g_t1[(size_t)B_ROWS * C_DIM];
__device__ __half g_t2[(size_t)B_ROWS * C_DIM];
__device__ __half g_yh[(size_t)B_ROWS * C_DIM];
__device__ __half g_vh[(size_t)B_ROWS * C_DIM];
__device__ __half g_d1[(size_t)B_ROWS * C_DIM];
__device__ __half g_d2[(size_t)B_ROWS * C_DIM];
__device__ __half g_u [(size_t)B_ROWS * C_DIM];          // u = v @ W1^T (fp16)
__device__ __half g_w1h [(size_t)C_DIM * C_DIM];
__device__ __half g_w2h [(size_t)C_DIM * C_DIM];
__device__ __half g_w3h [(size_t)C_DIM * C_DIM];
__device__ __half g_w2th[(size_t)C_DIM * C_DIM];
__device__ __half g_w3th[(size_t)C_DIM * C_DIM];
__device__ __half g_m13 [(size_t)C_DIM * C_DIM];         // m13[m,n] = (W1·W3)[n,m]

// ---------------- helpers ----------------
__device__ __forceinline__ uint32_t smem_u32(const void* p) {
    uint32_t a;
    asm("{ .reg .u64 t; cvta.to.shared.u64 t, %1; cvt.u32.u64 %0, t; }" : "=r"(a) : "l"(p));
    return a;
}

#define LDSM4(R0, R1, R2, R3, addr)                                                 \
    asm volatile("ldmatrix.sync.aligned.m8n8.x4.shared.b16 {%0,%1,%2,%3}, [%4];"    \
                 : "=r"(R0), "=r"(R1), "=r"(R2), "=r"(R3) : "r"(addr))

#define MMA_F16(C0, C1, C2, C3, A0, A1, A2, A3, Bb0, Bb1)                           \
    asm volatile(                                                                   \
        "mma.sync.aligned.m16n8k16.row.col.f32.f16.f16.f32 "                        \
        "{%0,%1,%2,%3}, {%4,%5,%6,%7}, {%8,%9}, {%0,%1,%2,%3};"                     \
        : "+f"(C0), "+f"(C1), "+f"(C2), "+f"(C3)                                    \
        : "r"(A0), "r"(A1), "r"(A2), "r"(A3), "r"(Bb0), "r"(Bb1))

constexpr int EPI_ELU      = 0;  // out0(h) = elu(c+bias), out1(h) = elu'
constexpr int EPI_ADDY     = 1;  // out0(f) = aux(f) + c + bias
constexpr int EPI_MULD     = 2;  // out0(h) = c * aux(h)
constexpr int EPI_MULD_DOT = 3;  // val = c*aux(h); out0(h)=val; acc += alpha*sum(val*aux2(h))
constexpr int EPI_STOREH   = 4;  // out0(h) = c

// NT GEMM: out[m,n] = sum_k A[m,k] * Bm[n,k]
// PDL: B (weights; never produced by immediate predecessor) is prefetched BEFORE
// griddepcontrol.wait; A (chain-dependent) only after.
template <int EPI>
__global__ void __launch_bounds__(GEMM_THREADS, 2)
gemm_nt(const __half* __restrict__ A, const __half* __restrict__ Bm,
        const float* __restrict__ bias,
        void* __restrict__ out0, void* __restrict__ out1,
        const void* __restrict__ aux, const __half* __restrict__ aux2,
        float alpha, float* __restrict__ acc)
{
    extern __shared__ __align__(16) char dsm[];
    const uint32_t sbase = (smem_u32(dsm) + 1023u) & ~1023u;

    const int tid  = threadIdx.x;
    const int lane = tid & 31;
    const int warp = tid >> 5;
    const int wm   = warp & 3;   // 4 warps along M (32 rows)
    const int wn   = warp >> 2;  // 2 warps along N (64 cols)
    const int g    = lane >> 2;
    const int t    = lane & 3;

    const int Lrow  = (lane & 7) | (((lane >> 3) & 1) << 3);
    const int khalf = lane >> 4;
    const int r7    = Lrow & 7;

    const int brow = blockIdx.y * TILE_M;
    const int bcol = blockIdx.x * TILE_N;
    const __half* Abase = A  + (size_t)brow * C_DIM;
    const __half* Bbase = Bm + (size_t)bcol * C_DIM;

    float c[2][8][4];
#pragma unroll
    for (int i = 0; i < 2; ++i)
#pragma unroll
        for (int j = 0; j < 8; ++j)
#pragma unroll
            for (int r = 0; r < 4; ++r) c[i][j][r] = 0.f;

#define LOADA(ch, st)                                                             \
    do {                                                                          \
        const uint32_t sa_ = sbase + (st) * STAGE_BYTES;                          \
        const __half* ag_ = Abase + (ch) * BKC;                                   \
        _Pragma("unroll")                                                         \
        for (int i_ = 0; i_ < 4; ++i_) {                                          \
            int l_ = i_ * GEMM_THREADS + tid; int r_ = l_ >> 3; int q_ = l_ & 7;  \
            uint32_t d_ = sa_ + (uint32_t)(r_ * 128) + (uint32_t)((q_ ^ (r_ & 7)) << 4); \
            const __half* s_ = ag_ + (size_t)r_ * C_DIM + q_ * 8;                 \
            asm volatile("cp.async.cg.shared.global [%0], [%1], 16;"              \
                         :: "r"(d_), "l"(s_) : "memory");                         \
        }                                                                         \
    } while (0)

#define LOADB(ch, st)                                                             \
    do {                                                                          \
        const uint32_t sb_ = sbase + (st) * STAGE_BYTES + A_STAGE_BYTES;          \
        const __half* bg_ = Bbase + (ch) * BKC;                                   \
        _Pragma("unroll")                                                         \
        for (int i_ = 0; i_ < 4; ++i_) {                                          \
            int l_ = i_ * GEMM_THREADS + tid; int r_ = l_ >> 3; int q_ = l_ & 7;  \
            uint32_t d_ = sb_ + (uint32_t)(r_ * 128) + (uint32_t)((q_ ^ (r_ & 7)) << 4); \
            const __half* s_ = bg_ + (size_t)r_ * C_DIM + q_ * 8;                 \
            asm volatile("cp.async.cg.shared.global [%0], [%1], 16;"              \
                         :: "r"(d_), "l"(s_) : "memory");                         \
        }                                                                         \
    } while (0)

    // B prefetch (safe pre-dependency), then wait for upstream grid, then A.
    LOADB(0, 0);
    LOADB(1, 1);
    asm volatile("griddepcontrol.wait;" ::: "memory");
    LOADA(0, 0);
    asm volatile("cp.async.commit_group;" ::: "memory");   // G0: B0,B1,A0
    LOADA(1, 1);
    asm volatile("cp.async.commit_group;" ::: "memory");   // G1: A1

#pragma unroll 1
    for (int ch = 0; ch < KCHUNKS; ++ch) {
        const int s = ch % NSTAGE;
        asm volatile("cp.async.wait_group 1;" ::: "memory");
        __syncthreads();

        if (ch + 2 < KCHUNKS) {
            const int s2 = (ch + 2) % NSTAGE;
            LOADA(ch + 2, s2);
            LOADB(ch + 2, s2);
        }
        asm volatile("cp.async.commit_group;" ::: "memory");

        const uint32_t sa = sbase + s * STAGE_BYTES;
        const uint32_t sb = sa + A_STAGE_BYTES;

        uint32_t arow[2], brow4[4];
#pragma unroll
        for (int mt = 0; mt < 2; ++mt)
            arow[mt] = sa + (uint32_t)((wm * 32 + mt * 16 + Lrow) * 128);
#pragma unroll
        for (int n2 = 0; n2 < 4; ++n2)
            brow4[n2] = sb + (uint32_t)((wn * 64 + n2 * 16 + Lrow) * 128);

#pragma unroll
        for (int ks = 0; ks < 4; ++ks) {
            const uint32_t xoff = (uint32_t)(((2 * ks + khalf) ^ r7) << 4);

            unsigned af[2][4];
#pragma unroll
            for (int mt = 0; mt < 2; ++mt)
                LDSM4(af[mt][0], af[mt][1], af[mt][2], af[mt][3], arow[mt] + xoff);

            unsigned bf[8][2];
#pragma unroll
            for (int n2 = 0; n2 < 4; ++n2)
                LDSM4(bf[2 * n2][0], bf[2 * n2 + 1][0],
                      bf[2 * n2][1], bf[2 * n2 + 1][1], brow4[n2] + xoff);

#pragma unroll
            for (int mt = 0; mt < 2; ++mt)
#pragma unroll
                for (int nt = 0; nt < 8; ++nt)
                    MMA_F16(c[mt][nt][0], c[mt][nt][1], c[mt][nt][2], c[mt][nt][3],
                            af[mt][0], af[mt][1], af[mt][2], af[mt][3],
                            bf[nt][0], bf[nt][1]);
        }
    }
#undef LOADA
#undef LOADB

    // ---------------- epilogue ----------------
    float rs[2][2];
    rs[0][0] = rs[0][1] = rs[1][0] = rs[1][1] = 0.f;

#pragma unroll
    for (int mt = 0; mt < 2; ++mt) {
        const int row0 = brow + wm * 32 + mt * 16 + g;
#pragma unroll
        for (int nt = 0; nt < 8; ++nt) {
            const int col = bcol + wn * 64 + nt * 8 + 2 * t;
#pragma unroll
            for (int h = 0; h < 2; ++h) {
                const int row = row0 + h * 8;
                const size_t idx = (size_t)row * C_DIM + col;
                float v0 = c[mt][nt][h * 2 + 0];
                float v1 = c[mt][nt][h * 2 + 1];
                if (EPI == EPI_ELU) {
                    float2 bb = *(const float2*)&bias[col];
                    float a0 = v0 + bb.x, a1 = v1 + bb.y;
                    float h0 = (a0 > 0.f) ? a0 : expm1f(a0);
                    float h1 = (a1 > 0.f) ? a1 : expm1f(a1);
                    float e0 = (a0 > 0.f) ? 1.f : h0 + 1.f;
                    float e1 = (a1 > 0.f) ? 1.f : h1 + 1.f;
                    *(__half2*)((__half*)out0 + idx) = __floats2half2_rn(h0, h1);
                    *(__half2*)((__half*)out1 + idx) = __floats2half2_rn(e0, e1);
                } else if (EPI == EPI_ADDY) {
                    float2 bb = *(const float2*)&bias[col];
                    float2 yv = *(const float2*)((const float*)aux + idx);
                    *(float2*)((float*)out0 + idx) =
                        make_float2(v0 + bb.x + yv.x, v1 + bb.y + yv.y);
                } else if (EPI == EPI_MULD) {
                    float2 dv = __half22float2(*(const __half2*)((const __half*)aux + idx));
                    *(__half2*)((__half*)out0 + idx) = __floats2half2_rn(v0 * dv.x, v1 * dv.y);
                } else if (EPI == EPI_MULD_DOT) {
                    float2 dv = __half22float2(*(const __half2*)((const __half*)aux + idx));
                    float n0 = v0 * dv.x, n1 = v1 * dv.y;
                    *(__half2*)((__half*)out0 + idx) = __floats2half2_rn(n0, n1);
                    float2 uu = __half22float2(*(const __half2*)(aux2 + idx));
                    rs[mt][h] += n0 * uu.x + n1 * uu.y;
                } else {  // EPI_STOREH
                    *(__half2*)((__half*)out0 + idx) = __floats2half2_rn(v0, v1);
                }
            }
        }
    }

    if (EPI == EPI_MULD_DOT) {
#pragma unroll
        for (int mt = 0; mt < 2; ++mt)
#pragma unroll
            for (int h = 0; h < 2; ++h) {
                float s = rs[mt][h];
                s += __shfl_xor_sync(0xffffffffu, s, 1);
                s += __shfl_xor_sync(0xffffffffu, s, 2);
                if (t == 0)
                    atomicAdd(&acc[brow + wm * 32 + mt * 16 + g + h * 8], alpha * s);
            }
    }

    // signal dependents (all stores above are pre-trigger)
    asm volatile("griddepcontrol.launch_dependents;" ::: "memory");
}

// ---------------- fused prep kernels ----------------
// z=0: W1 -> w1h ; z=1: W2 -> w2h + w2th ; z=2: W3 -> w3h + w3th
__global__ void prep_w(const float* __restrict__ W1, const float* __restrict__ W2,
                       const float* __restrict__ W3,
                       __half* __restrict__ w1h, __half* __restrict__ w2h,
                       __half* __restrict__ w3h,
                       __half* __restrict__ w2th, __half* __restrict__ w3th)
{
    __shared__ float tile[32][33];
    const int z = blockIdx.z;
    const float* in = (z == 0) ? W1 : (z == 1) ? W2 : W3;
    __half* oc = (z == 0) ? w1h : (z == 1) ? w2h : w3h;
    __half* ot = (z == 1) ? w2th : (z == 2) ? w3th : nullptr;

    int x = blockIdx.x * 32 + threadIdx.x;
    int y = blockIdx.y * 32 + threadIdx.y;
#pragma unroll
    for (int i = 0; i < 32; i += 8) {
        float v = in[(size_t)(y + i) * C_DIM + x];
        tile[threadIdx.y + i][threadIdx.x] = v;
        oc[(size_t)(y + i) * C_DIM + x] = __float2half_rn(v);
    }
    if (ot) {
        __syncthreads();
        int tx = blockIdx.y * 32 + threadIdx.x;
        int ty = blockIdx.x * 32 + threadIdx.y;
#pragma unroll
        for (int i = 0; i < 32; i += 8)
            ot[(size_t)(ty + i) * C_DIM + tx] = __float2half_rn(tile[threadIdx.x][threadIdx.y + i]);
    }
}

// yh, vh (f2h) + ldout init
__global__ void prep_d(const float* __restrict__ y, const float* __restrict__ v,
                       const float* __restrict__ ldj,
                       __half* __restrict__ yh, __half* __restrict__ vh,
                       float* __restrict__ ldout)
{
    int j = blockIdx.x * 256 + threadIdx.x;
    int i = j * 4;
    float4 a = *(const float4*)(y + i);
    __half2 lo = __floats2half2_rn(a.x, a.y);
    __half2 hi = __floats2half2_rn(a.z, a.w);
    *(uint2*)(yh + i) = make_uint2(*(unsigned*)&lo, *(unsigned*)&hi);
    float4 b = *(const float4*)(v + i);
    lo = __floats2half2_rn(b.x, b.y);
    hi = __floats2half2_rn(b.z, b.w);
    *(uint2*)(vh + i) = make_uint2(*(unsigned*)&lo, *(unsigned*)&hi);
    if (j < B_ROWS) ldout[j] = ldj[j];
}

// ---------------- launch ----------------
template <int EPI>
static void launch_gemm(dim3 grid, const __half* A, const __half* Bm, const float* bias,
                        void* o0, void* o1, const void* aux, const __half* aux2,
                        float alpha, float* acc)
{
    cudaLaunchConfig_t cfg = {};
    cfg.gridDim = grid;
    cfg.blockDim = dim3(GEMM_THREADS, 1, 1);
    cfg.dynamicSmemBytes = SMEM_TOTAL;
    cfg.stream = 0;
    cudaLaunchAttribute at[1];
    at[0].id = cudaLaunchAttributeProgrammaticStreamSerialization;
    at[0].val.programmaticStreamSerializationAllowed = 1;
    cfg.attrs = at;
    cfg.numAttrs = 1;
    cudaLaunchKernelEx(&cfg, gemm_nt<EPI>, A, Bm, bias, o0, o1, aux, aux2, alpha, acc);
}

extern "C" void kernel_launch(void* const* d_in, const int* in_sizes, int n_in,
                              void* d_out, int out_size)
{
    (void)in_sizes; (void)n_in; (void)out_size;

    const float* y   = (const float*)d_in[0];
    const float* ldj = (const float*)d_in[1];
    const float* v   = (const float*)d_in[2];
    const float* W1  = (const float*)d_in[3];
    const float* b1  = (const float*)d_in[4];
    const float* W2  = (const float*)d_in[5];
    const float* b2  = (const float*)d_in[6];
    const float* W3  = (const float*)d_in[7];
    const float* b3  = (const float*)d_in[8];

    float* zout  = (float*)d_out;
    float* ldout = zout + (size_t)B_ROWS * C_DIM;

    __half *h1, *h2, *t1, *t2, *yh, *vh, *d1, *d2, *m13, *u;
    __half *w1h, *w2h, *w3h, *w2th, *w3th;
    cudaGetSymbolAddress((void**)&h1,   g_h1);
    cudaGetSymbolAddress((void**)&h2,   g_h2);
    cudaGetSymbolAddress((void**)&t1,   g_t1);
    cudaGetSymbolAddress((void**)&t2,   g_t2);
    cudaGetSymbolAddress((void**)&yh,   g_yh);
    cudaGetSymbolAddress((void**)&vh,   g_vh);
    cudaGetSymbolAddress((void**)&d1,   g_d1);
    cudaGetSymbolAddress((void**)&d2,   g_d2);
    cudaGetSymbolAddress((void**)&u,    g_u);
    cudaGetSymbolAddress((void**)&m13,  g_m13);
    cudaGetSymbolAddress((void**)&w1h,  g_w1h);
    cudaGetSymbolAddress((void**)&w2h,  g_w2h);
    cudaGetSymbolAddress((void**)&w3h,  g_w3h);
    cudaGetSymbolAddress((void**)&w2th, g_w2th);
    cudaGetSymbolAddress((void**)&w3th, g_w3th);

    cudaFuncSetAttribute(gemm_nt<EPI_ELU     >, cudaFuncAttributeMaxDynamicSharedMemorySize, SMEM_TOTAL);
    cudaFuncSetAttribute(gemm_nt<EPI_ADDY    >, cudaFuncAttributeMaxDynamicSharedMemorySize, SMEM_TOTAL);
    cudaFuncSetAttribute(gemm_nt<EPI_MULD    >, cudaFuncAttributeMaxDynamicSharedMemorySize, SMEM_TOTAL);
    cudaFuncSetAttribute(gemm_nt<EPI_MULD_DOT>, cudaFuncAttributeMaxDynamicSharedMemorySize, SMEM_TOTAL);
    cudaFuncSetAttribute(gemm_nt<EPI_STOREH  >, cudaFuncAttributeMaxDynamicSharedMemorySize, SMEM_TOTAL);

    // #1, #2: fused prep
    prep_w<<<dim3(32, 32, 3), dim3(32, 8)>>>(W1, W2, W3, w1h, w2h, w3h, w2th, w3th);
    prep_d<<<B_ROWS * C_DIM / 1024, 256>>>(y, v, ldj, yh, vh, ldout);

    dim3 ggrid(C_DIM / TILE_N, B_ROWS / TILE_M);   // (8, 128)
    dim3 sgrid(C_DIM / TILE_N, C_DIM / TILE_M);    // (8, 8)

    // #3: u = v @ W1^T (independent of forward)
    launch_gemm<EPI_STOREH>(ggrid, vh, w1h, nullptr, u, nullptr, nullptr, nullptr, 0.f, nullptr);
    // #4: m13[m,n] = (W1·W3)[n,m]
    launch_gemm<EPI_STOREH>(sgrid, w3th, w1h, nullptr, m13, nullptr, nullptr, nullptr, 0.f, nullptr);

    // #5, #6 (profiled), #7: forward
    launch_gemm<EPI_ELU >(ggrid, yh, w1h, b1, h1, d1, nullptr, nullptr, 0.f, nullptr);
    launch_gemm<EPI_ELU >(ggrid, h1, w2h, b2, h2, d2, nullptr, nullptr, 0.f, nullptr);
    launch_gemm<EPI_ADDY>(ggrid, h2, w3h, b3, zout, nullptr, y, nullptr, 0.f, nullptr);

    // power-series iterations: 2 GEMMs per k
    for (int k = 1; k <= N_ITERS; ++k) {
        if (k == 1)
            launch_gemm<EPI_MULD>(ggrid, vh, w3th, nullptr, t1, nullptr, d2, nullptr, 0.f, nullptr);
        else
            launch_gemm<EPI_MULD>(ggrid, t2, m13, nullptr, t1, nullptr, d2, nullptr, 0.f, nullptr);
        const float alpha = ((k & 1) ? 1.f : -1.f) / (float)k;
        launch_gemm<EPI_MULD_DOT>(ggrid, t1, w2th, nullptr, t2, nullptr, d1, u, alpha, ldout);
    }
}